// round 1
// baseline (speedup 1.0000x reference)
#include <cuda_runtime.h>
#include <cstdint>

#define D   768
#define DV  (D / 4)    // 192 float4 per row
#define E   8
#define RB  4          // rows per warp-batch

__global__ __launch_bounds__(256, 2)
void router_kernel(const float* __restrict__ h,
                   const float* __restrict__ gw,
                   const float* __restrict__ gb,
                   float* __restrict__ out, int B) {
    __shared__ float4 w_sh[E * DV];   // 24 KB
    __shared__ float  b_sh[E];

    const float4* gw4 = reinterpret_cast<const float4*>(gw);
    for (int i = threadIdx.x; i < E * DV; i += blockDim.x)
        w_sh[i] = gw4[i];
    if (threadIdx.x < E) b_sh[threadIdx.x] = gb[threadIdx.x];
    __syncthreads();

    const int lane   = threadIdx.x & 31;
    const int warp   = threadIdx.x >> 5;
    const int gwarp  = blockIdx.x * (blockDim.x >> 5) + warp;
    const int nwarps = gridDim.x * (blockDim.x >> 5);
    const int nbatch = (B + RB - 1) / RB;

    float* out_idx = out;                       // [B,2] indices (as float)
    float* out_wt  = out + (size_t)2 * B;       // [B,2] weights
    float* out_lg  = out + (size_t)4 * B;       // [B,8] logits

    const float4* h4 = reinterpret_cast<const float4*>(h);

    for (int batch = gwarp; batch < nbatch; batch += nwarps) {
        const int row0 = batch * RB;

        float v[RB * E];
        #pragma unroll
        for (int i = 0; i < RB * E; i++) v[i] = 0.0f;

        // row pointers (clamped so tail loads stay in-bounds)
        const float4* hr[RB];
        #pragma unroll
        for (int r = 0; r < RB; r++) {
            int rr = row0 + r; if (rr > B - 1) rr = B - 1;
            hr[r] = h4 + (size_t)rr * DV;
        }

        #pragma unroll
        for (int j = 0; j < DV / 32; j++) {      // 6 iterations
            const int k4 = j * 32 + lane;
            float4 wv[E];
            #pragma unroll
            for (int e = 0; e < E; e++) wv[e] = w_sh[e * DV + k4];
            #pragma unroll
            for (int r = 0; r < RB; r++) {
                const float4 x = hr[r][k4];      // coalesced LDG.128
                #pragma unroll
                for (int e = 0; e < E; e++) {
                    v[r * E + e] += x.x * wv[e].x + x.y * wv[e].y
                                  + x.z * wv[e].z + x.w * wv[e].w;
                }
            }
        }

        // Butterfly transpose-reduction: after 5 steps, lane l holds the full
        // sum of value index l  (l = r*8 + e).  31 shuffles total.
        #pragma unroll
        for (int off = 16; off >= 1; off >>= 1) {
            const bool up = (lane & off) != 0;
            #pragma unroll
            for (int i = 0; i < off; i++) {
                float send = up ? v[i] : v[i + off];
                float recv = __shfl_xor_sync(0xffffffffu, send, off);
                v[i] = (up ? v[i + off] : v[i]) + recv;
            }
        }

        const int r   = lane >> 3;
        const int e   = lane & 7;
        const int row = row0 + r;
        const float logit = v[0] + b_sh[e];

        if (row < B)
            out_lg[(size_t)row * E + e] = logit;   // 32 consecutive floats/warp

        // gather this row's 8 logits (group base = lane & 24)
        float lv[8];
        #pragma unroll
        for (int k = 0; k < 8; k++)
            lv[k] = __shfl_sync(0xffffffffu, logit, (lane & 24) | k);

        if (e == 0 && row < B) {
            // top-1: strict >, lowest index wins ties (matches lax.top_k)
            int i1 = 0; float v1 = lv[0];
            #pragma unroll
            for (int k = 1; k < 8; k++)
                if (lv[k] > v1) { v1 = lv[k]; i1 = k; }
            // top-2 among the rest
            int i2 = (i1 == 0) ? 1 : 0; float v2 = lv[i2];
            #pragma unroll
            for (int k = 0; k < 8; k++)
                if (k != i1 && lv[k] > v2) { v2 = lv[k]; i2 = k; }

            const float t  = __expf(v2 - v1);     // <= 1
            const float w1 = 1.0f / (1.0f + t);
            const float w2 = t * w1;

            out_idx[(size_t)row * 2]     = (float)i1;
            out_idx[(size_t)row * 2 + 1] = (float)i2;
            out_wt [(size_t)row * 2]     = w1;
            out_wt [(size_t)row * 2 + 1] = w2;
        }
    }
}

extern "C" void kernel_launch(void* const* d_in, const int* in_sizes, int n_in,
                              void* d_out, int out_size) {
    const float* h  = (const float*)d_in[0];   // [B, 768]
    const float* gw = (const float*)d_in[1];   // [8, 768]
    const float* gb = (const float*)d_in[2];   // [8]
    float* out = (float*)d_out;

    const int B = in_sizes[0] / D;             // 32768

    const int threads = 256;
    const int blocks  = 296;                   // ~2 CTAs/SM, grid-stride over batches
    router_kernel<<<blocks, threads>>>(h, gw, gb, out, B);
}

// round 2
// speedup vs baseline: 2.7612x; 2.7612x over previous
#include <cuda_runtime.h>
#include <cstdint>

#define D   768
#define DV  (D / 4)    // 192 float4 per row
#define E   8
#define RB  4          // rows per warp-batch

__global__ __launch_bounds__(256, 4)   // force <=64 regs -> 32 warps/SM
void router_kernel(const float* __restrict__ h,
                   const float* __restrict__ gw,
                   const float* __restrict__ gb,
                   float* __restrict__ out, int B) {
    __shared__ float4 w_sh[E * DV];   // 24 KB
    __shared__ float  b_sh[E];

    const float4* gw4 = reinterpret_cast<const float4*>(gw);
    for (int i = threadIdx.x; i < E * DV; i += blockDim.x)
        w_sh[i] = gw4[i];
    if (threadIdx.x < E) b_sh[threadIdx.x] = gb[threadIdx.x];
    __syncthreads();

    const int lane   = threadIdx.x & 31;
    const int warp   = threadIdx.x >> 5;
    const int gwarp  = blockIdx.x * (blockDim.x >> 5) + warp;
    const int nwarps = gridDim.x * (blockDim.x >> 5);
    const int nbatch = (B + RB - 1) / RB;

    float* out_idx = out;                       // [B,2] indices (as float)
    float* out_wt  = out + (size_t)2 * B;       // [B,2] weights
    float* out_lg  = out + (size_t)4 * B;       // [B,8] logits

    const float4* h4 = reinterpret_cast<const float4*>(h);

    for (int batch = gwarp; batch < nbatch; batch += nwarps) {
        const int row0 = batch * RB;
        // single base pointer; row offsets are compile-time immediates
        const float4* hb = h4 + (size_t)row0 * DV;

        float acc[RB * E];
        #pragma unroll
        for (int i = 0; i < RB * E; i++) acc[i] = 0.0f;

        #pragma unroll 1
        for (int j = 0; j < DV / 32; j++) {      // 6 iterations
            const int k4 = j * 32 + lane;
            // 4 independent coalesced LDG.128 (MLP=4), imm row offsets
            const float4 x0 = hb[k4];
            const float4 x1 = hb[k4 + DV];
            const float4 x2 = hb[k4 + 2 * DV];
            const float4 x3 = hb[k4 + 3 * DV];
            #pragma unroll
            for (int e = 0; e < E; e++) {
                const float4 w = w_sh[e * DV + k4];
                acc[0 * E + e] += x0.x * w.x + x0.y * w.y + x0.z * w.z + x0.w * w.w;
                acc[1 * E + e] += x1.x * w.x + x1.y * w.y + x1.z * w.z + x1.w * w.w;
                acc[2 * E + e] += x2.x * w.x + x2.y * w.y + x2.z * w.z + x2.w * w.w;
                acc[3 * E + e] += x3.x * w.x + x3.y * w.y + x3.z * w.z + x3.w * w.w;
            }
        }

        // Butterfly transpose-reduction: after 5 steps, lane l holds the full
        // sum of value index l  (l = r*8 + e).  31 shuffles total.
        #pragma unroll
        for (int off = 16; off >= 1; off >>= 1) {
            const bool up = (lane & off) != 0;
            #pragma unroll
            for (int i = 0; i < off; i++) {
                float send = up ? acc[i] : acc[i + off];
                float recv = __shfl_xor_sync(0xffffffffu, send, off);
                acc[i] = (up ? acc[i + off] : acc[i]) + recv;
            }
        }

        const int r   = lane >> 3;
        const int e   = lane & 7;
        const int row = row0 + r;
        const float logit = acc[0] + b_sh[e];

        if (row < B)
            out_lg[(size_t)row * E + e] = logit;   // 32 consecutive floats/warp

        // gather this row's 8 logits (group base = lane & 24)
        float lv[8];
        #pragma unroll
        for (int k = 0; k < 8; k++)
            lv[k] = __shfl_sync(0xffffffffu, logit, (lane & 24) | k);

        if (e == 0 && row < B) {
            // top-1: strict >, lowest index wins ties (matches lax.top_k)
            int i1 = 0; float v1 = lv[0];
            #pragma unroll
            for (int k = 1; k < 8; k++)
                if (lv[k] > v1) { v1 = lv[k]; i1 = k; }
            // top-2 among the rest
            int i2 = (i1 == 0) ? 1 : 0; float v2 = lv[i2];
            #pragma unroll
            for (int k = 0; k < 8; k++)
                if (k != i1 && lv[k] > v2) { v2 = lv[k]; i2 = k; }

            const float t  = __expf(v2 - v1);     // <= 1
            const float w1 = 1.0f / (1.0f + t);
            const float w2 = t * w1;

            out_idx[(size_t)row * 2]     = (float)i1;
            out_idx[(size_t)row * 2 + 1] = (float)i2;
            out_wt [(size_t)row * 2]     = w1;
            out_wt [(size_t)row * 2 + 1] = w2;
        }
    }
}

extern "C" void kernel_launch(void* const* d_in, const int* in_sizes, int n_in,
                              void* d_out, int out_size) {
    const float* h  = (const float*)d_in[0];   // [B, 768]
    const float* gw = (const float*)d_in[1];   // [8, 768]
    const float* gb = (const float*)d_in[2];   // [8]
    float* out = (float*)d_out;

    const int B = in_sizes[0] / D;             // 32768

    // 512 CTAs x 8 warps = 4096 warps -> exactly 2 batches per warp,
    // all resident in one wave at occupancy 4 (592 slots on 148 SMs).
    const int threads = 256;
    const int blocks  = 512;
    router_kernel<<<blocks, threads>>>(h, gw, gb, out, B);
}

// round 3
// speedup vs baseline: 2.9607x; 1.0722x over previous
#include <cuda_runtime.h>
#include <cstdint>

#define D   768
#define DV  (D / 4)    // 192 float4 per row
#define E   8
#define RB  4          // rows per warp-batch

typedef unsigned long long ull;

// packed 2-wide fp32 FMA: d = a*b + d (elementwise on 2 lanes)
__device__ __forceinline__ void ffma2(ull& d, ull a, ull b) {
    asm("fma.rn.f32x2 %0, %1, %2, %0;" : "+l"(d) : "l"(a), "l"(b));
}
// broadcast one f32 into both halves of a b64
__device__ __forceinline__ ull bcast2(float x) {
    ull r;
    asm("mov.b64 %0, {%1, %1};" : "=l"(r) : "r"(__float_as_uint(x)));
    return r;
}
#define COMP(v, c) ((c) == 0 ? (v).x : (c) == 1 ? (v).y : (c) == 2 ? (v).z : (v).w)

__global__ __launch_bounds__(256, 4)   // 64 regs -> 32 warps/SM
void router_kernel(const float* __restrict__ h,
                   const float* __restrict__ gw,
                   const float* __restrict__ gb,
                   float* __restrict__ out, int B) {
    // w transposed+packed: ws2[(c*2+g)*DV + k4] = float4 of experts {4g..4g+3},
    // scalar column (4*k4 + c). Read as ulonglong2 -> two expert-pairs.
    __shared__ float4 ws2[8 * DV];    // 24 KB
    __shared__ float  b_sh[E];

    for (int i = threadIdx.x; i < 8 * DV; i += blockDim.x) {
        const int k4 = i % DV;
        const int cg = i / DV;        // c*2+g
        const int c  = cg >> 1;
        const int g  = cg & 1;
        const int col = 4 * k4 + c;
        ws2[i] = make_float4(gw[(4 * g + 0) * D + col],
                             gw[(4 * g + 1) * D + col],
                             gw[(4 * g + 2) * D + col],
                             gw[(4 * g + 3) * D + col]);
    }
    if (threadIdx.x < E) b_sh[threadIdx.x] = gb[threadIdx.x];
    __syncthreads();

    const ulonglong2* wsu = reinterpret_cast<const ulonglong2*>(ws2);

    const int lane   = threadIdx.x & 31;
    const int warp   = threadIdx.x >> 5;
    const int gwarp  = blockIdx.x * (blockDim.x >> 5) + warp;
    const int nwarps = gridDim.x * (blockDim.x >> 5);
    const int nbatch = (B + RB - 1) / RB;

    float* out_idx = out;                       // [B,2] indices (as float)
    float* out_wt  = out + (size_t)2 * B;       // [B,2] weights
    float* out_lg  = out + (size_t)4 * B;       // [B,8] logits

    const float4* h4 = reinterpret_cast<const float4*>(h);

    for (int batch = gwarp; batch < nbatch; batch += nwarps) {
        const int row0 = batch * RB;
        const float4* hb = h4 + (size_t)row0 * DV;

        // acc2[r][p] packs experts (2p, 2p+1) for row r
        ull acc2[RB][4];
        #pragma unroll
        for (int r = 0; r < RB; r++)
            #pragma unroll
            for (int p = 0; p < 4; p++) acc2[r][p] = 0ull;

        #pragma unroll 1
        for (int j = 0; j < DV / 32; j++) {      // 6 iterations
            const int k4 = j * 32 + lane;
            // 4 independent coalesced LDG.128, compile-time row offsets
            const float4 x0 = hb[k4];
            const float4 x1 = hb[k4 + DV];
            const float4 x2 = hb[k4 + 2 * DV];
            const float4 x3 = hb[k4 + 3 * DV];
            #pragma unroll
            for (int c = 0; c < 4; c++) {
                // experts 0-3 and 4-7 of scalar column 4*k4+c (conflict-free)
                const ulonglong2 wg0 = wsu[(c * 2 + 0) * DV + k4];
                const ulonglong2 wg1 = wsu[(c * 2 + 1) * DV + k4];
                {
                    const ull xb = bcast2(COMP(x0, c));
                    ffma2(acc2[0][0], wg0.x, xb); ffma2(acc2[0][1], wg0.y, xb);
                    ffma2(acc2[0][2], wg1.x, xb); ffma2(acc2[0][3], wg1.y, xb);
                }
                {
                    const ull xb = bcast2(COMP(x1, c));
                    ffma2(acc2[1][0], wg0.x, xb); ffma2(acc2[1][1], wg0.y, xb);
                    ffma2(acc2[1][2], wg1.x, xb); ffma2(acc2[1][3], wg1.y, xb);
                }
                {
                    const ull xb = bcast2(COMP(x2, c));
                    ffma2(acc2[2][0], wg0.x, xb); ffma2(acc2[2][1], wg0.y, xb);
                    ffma2(acc2[2][2], wg1.x, xb); ffma2(acc2[2][3], wg1.y, xb);
                }
                {
                    const ull xb = bcast2(COMP(x3, c));
                    ffma2(acc2[3][0], wg0.x, xb); ffma2(acc2[3][1], wg0.y, xb);
                    ffma2(acc2[3][2], wg1.x, xb); ffma2(acc2[3][3], wg1.y, xb);
                }
            }
        }

        // unpack to 32 scalars (acc[r*8+e]) for the butterfly
        float acc[RB * E];
        #pragma unroll
        for (int r = 0; r < RB; r++)
            #pragma unroll
            for (int p = 0; p < 4; p++) {
                uint32_t lo, hi;
                asm("mov.b64 {%0, %1}, %2;" : "=r"(lo), "=r"(hi) : "l"(acc2[r][p]));
                acc[r * E + 2 * p]     = __uint_as_float(lo);
                acc[r * E + 2 * p + 1] = __uint_as_float(hi);
            }

        // Butterfly transpose-reduction: lane l ends with sum of index l.
        #pragma unroll
        for (int off = 16; off >= 1; off >>= 1) {
            const bool up = (lane & off) != 0;
            #pragma unroll
            for (int i = 0; i < off; i++) {
                float send = up ? acc[i] : acc[i + off];
                float recv = __shfl_xor_sync(0xffffffffu, send, off);
                acc[i] = (up ? acc[i + off] : acc[i]) + recv;
            }
        }

        const int r   = lane >> 3;
        const int e   = lane & 7;
        const int row = row0 + r;
        const float logit = acc[0] + b_sh[e];

        if (row < B)
            out_lg[(size_t)row * E + e] = logit;

        float lv[8];
        #pragma unroll
        for (int k = 0; k < 8; k++)
            lv[k] = __shfl_sync(0xffffffffu, logit, (lane & 24) | k);

        if (e == 0 && row < B) {
            int i1 = 0; float v1 = lv[0];
            #pragma unroll
            for (int k = 1; k < 8; k++)
                if (lv[k] > v1) { v1 = lv[k]; i1 = k; }
            int i2 = (i1 == 0) ? 1 : 0; float v2 = lv[i2];
            #pragma unroll
            for (int k = 0; k < 8; k++)
                if (k != i1 && lv[k] > v2) { v2 = lv[k]; i2 = k; }

            const float t  = __expf(v2 - v1);
            const float w1 = 1.0f / (1.0f + t);
            const float w2 = t * w1;

            out_idx[(size_t)row * 2]     = (float)i1;
            out_idx[(size_t)row * 2 + 1] = (float)i2;
            out_wt [(size_t)row * 2]     = w1;
            out_wt [(size_t)row * 2 + 1] = w2;
        }
    }
}

extern "C" void kernel_launch(void* const* d_in, const int* in_sizes, int n_in,
                              void* d_out, int out_size) {
    const float* h  = (const float*)d_in[0];   // [B, 768]
    const float* gw = (const float*)d_in[1];   // [8, 768]
    const float* gb = (const float*)d_in[2];   // [8]
    float* out = (float*)d_out;

    const int B = in_sizes[0] / D;             // 32768

    const int threads = 256;
    const int blocks  = 512;                   // 4096 warps -> exactly 2 batches/warp
    router_kernel<<<blocks, threads>>>(h, gw, gb, out, B);
}